// round 4
// baseline (speedup 1.0000x reference)
#include <cuda_runtime.h>
#include <math_constants.h>

// Batched nearest-neighbor argmin + gather (HBM-streaming).
//   y: [B,2] f32, Y_surf: [B,2,G] f32, U_grid: [2,G] f32, out: [B,2] f32
//   out[b,:] = U_grid[:, argmin_g ||Y_surf[b,:,g] - y[b,:]||^2]
//
// Persistent grid: numSM*occ CTAs, each owning a CONTIGUOUS chunk of samples
// (contiguous ~190KB DRAM read per CTA -> fewer stream restarts, no per-sample
// CTA dispatch). Inner loop identical to R3: 128 thr, float4 x2 unroll,
// 4 independent argmin accumulators, exact first-index tie-break.

#define NT 128

struct Acc { float d[4]; int g[4]; };

__device__ __forceinline__ void proc4(const float4& a, const float4& c, int g,
                                      float y0, float y1, Acc& acc) {
    float dx, dz, d;
    dx = a.x - y0; dz = c.x - y1; d = dx * dx + dz * dz;
    if (d < acc.d[0]) { acc.d[0] = d; acc.g[0] = g + 0; }
    dx = a.y - y0; dz = c.y - y1; d = dx * dx + dz * dz;
    if (d < acc.d[1]) { acc.d[1] = d; acc.g[1] = g + 1; }
    dx = a.z - y0; dz = c.z - y1; d = dx * dx + dz * dz;
    if (d < acc.d[2]) { acc.d[2] = d; acc.g[2] = g + 2; }
    dx = a.w - y0; dz = c.w - y1; d = dx * dx + dz * dz;
    if (d < acc.d[3]) { acc.d[3] = d; acc.g[3] = g + 3; }
}

__global__ __launch_bounds__(NT, 12)
void lqr_argmin_pers_kernel(const float* __restrict__ y,
                            const float* __restrict__ Ys,
                            const float* __restrict__ Ug,
                            float* __restrict__ out,
                            int B, int G) {
    const int tid = threadIdx.x;
    const int w   = tid >> 5;
    __shared__ float sb[NT / 32];
    __shared__ int   si[NT / 32];

    // Contiguous chunk assignment: CTA i owns [b0, b1).
    const int nCta = gridDim.x;
    const int q = B / nCta, r = B % nCta;
    const int i = blockIdx.x;
    const int b0 = i * q + min(i, r);
    const int b1 = b0 + q + (i < r ? 1 : 0);

    const int n4 = G >> 2;  // G % 4 == 0 (G = 2500)

    for (int b = b0; b < b1; ++b) {
        const float y0 = y[2 * b + 0];
        const float y1 = y[2 * b + 1];

        const float4* __restrict__ v0 =
            reinterpret_cast<const float4*>(Ys + (size_t)b * 2 * G);
        const float4* __restrict__ v1 = v0 + n4;

        Acc acc;
        #pragma unroll
        for (int k = 0; k < 4; k++) { acc.d[k] = CUDART_INF_F; acc.g[k] = 0; }

        int j = tid;
        for (; j + NT < n4; j += 2 * NT) {
            float4 a0 = v0[j];
            float4 a1 = v0[j + NT];
            float4 c0 = v1[j];
            float4 c1 = v1[j + NT];
            proc4(a0, c0, j << 2,        y0, y1, acc);
            proc4(a1, c1, (j + NT) << 2, y0, y1, acc);
        }
        if (j < n4) {
            float4 a = v0[j];
            float4 c = v1[j];
            proc4(a, c, j << 2, y0, y1, acc);
        }

        // Merge 4 accumulators: min d2, tie -> min idx (jnp.argmin first-min).
        float best = acc.d[0];
        int   bidx = acc.g[0];
        #pragma unroll
        for (int k = 1; k < 4; k++) {
            if (acc.d[k] < best || (acc.d[k] == best && acc.g[k] < bidx)) {
                best = acc.d[k]; bidx = acc.g[k];
            }
        }

        #pragma unroll
        for (int off = 16; off > 0; off >>= 1) {
            float ob = __shfl_down_sync(0xffffffffu, best, off);
            int   oi = __shfl_down_sync(0xffffffffu, bidx, off);
            if (ob < best || (ob == best && oi < bidx)) { best = ob; bidx = oi; }
        }

        if ((tid & 31) == 0) { sb[w] = best; si[w] = bidx; }
        __syncthreads();

        if (w == 0) {
            const int nw = NT / 32;
            best = (tid < nw) ? sb[tid] : CUDART_INF_F;
            bidx = (tid < nw) ? si[tid] : 0x7fffffff;
            #pragma unroll
            for (int off = 16; off > 0; off >>= 1) {
                float ob = __shfl_down_sync(0xffffffffu, best, off);
                int   oi = __shfl_down_sync(0xffffffffu, bidx, off);
                if (ob < best || (ob == best && oi < bidx)) { best = ob; bidx = oi; }
            }
            if (tid == 0) {
                out[2 * b + 0] = Ug[bidx];
                out[2 * b + 1] = Ug[(size_t)G + bidx];
            }
        }
        __syncthreads();  // protect sb/si reuse next iteration
    }
}

extern "C" void kernel_launch(void* const* d_in, const int* in_sizes, int n_in,
                              void* d_out, int out_size) {
    const float* y  = (const float*)d_in[0];   // [B, 2]
    const float* Ys = (const float*)d_in[1];   // [B, 2, G]
    const float* Ug = (const float*)d_in[2];   // [2, G]
    float* out = (float*)d_out;                // [B, 2]

    const int B = in_sizes[0] / 2;
    const int G = in_sizes[2] / 2;

    // Persistent grid: exactly (SMs x resident CTAs/SM), queried so a
    // mis-guess can't create a 1.x-wave tail.
    int dev = 0;
    cudaGetDevice(&dev);
    int numSM = 148;
    cudaDeviceGetAttribute(&numSM, cudaDevAttrMultiProcessorCount, dev);
    int maxB = 12;
    cudaOccupancyMaxActiveBlocksPerMultiprocessor(&maxB, lqr_argmin_pers_kernel,
                                                  NT, 0);
    int grid = numSM * maxB;
    if (grid > B) grid = B;
    if (grid < 1) grid = 1;

    lqr_argmin_pers_kernel<<<grid, NT>>>(y, Ys, Ug, out, B, G);
}

// round 5
// speedup vs baseline: 1.0394x; 1.0394x over previous
#include <cuda_runtime.h>
#include <math_constants.h>

// Batched nearest-neighbor argmin + gather (HBM/LTS-streaming, ~95% of LTS cap).
//   y: [B,2] f32, Y_surf: [B,2,G] f32, U_grid: [2,G] f32, out: [B,2] f32
//   out[b,:] = U_grid[:, argmin_g ||Y_surf[b,:,g] - y[b,:]||^2]
//
// Block-per-sample (128 thr), float4 __ldcs streaming loads, x2 unroll
// (4 independent LDG.128 in flight), 4 independent argmin accumulators
// (depth-1 update chains), packed-u64 (d2bits<<32 | idx) min reduction
// giving exact jnp.argmin first-index tie-break.

#define NT 128

struct Acc { float d[4]; int g[4]; };

__device__ __forceinline__ void proc4(const float4& a, const float4& c, int g,
                                      float y0, float y1, Acc& acc) {
    float dx, dz, d;
    dx = a.x - y0; dz = c.x - y1; d = dx * dx + dz * dz;
    if (d < acc.d[0]) { acc.d[0] = d; acc.g[0] = g + 0; }
    dx = a.y - y0; dz = c.y - y1; d = dx * dx + dz * dz;
    if (d < acc.d[1]) { acc.d[1] = d; acc.g[1] = g + 1; }
    dx = a.z - y0; dz = c.z - y1; d = dx * dx + dz * dz;
    if (d < acc.d[2]) { acc.d[2] = d; acc.g[2] = g + 2; }
    dx = a.w - y0; dz = c.w - y1; d = dx * dx + dz * dz;
    if (d < acc.d[3]) { acc.d[3] = d; acc.g[3] = g + 3; }
}

// d2 >= 0 always, so IEEE bit pattern is order-monotone as u32.
// key = (bits(d2) << 32) | idx : min(key) == (min d2, tie -> min idx).
__device__ __forceinline__ unsigned long long pack(float d, int g) {
    return ((unsigned long long)__float_as_uint(d) << 32) | (unsigned)g;
}

__global__ __launch_bounds__(NT)
void lqr_argmin_kernel(const float* __restrict__ y,
                       const float* __restrict__ Ys,
                       const float* __restrict__ Ug,
                       float* __restrict__ out,
                       int G) {
    const int b   = blockIdx.x;
    const int tid = threadIdx.x;

    const float y0 = y[2 * b + 0];
    const float y1 = y[2 * b + 1];

    const float4* __restrict__ v0 =
        reinterpret_cast<const float4*>(Ys + (size_t)b * 2 * G);
    const float4* __restrict__ v1 = v0 + (G >> 2);
    const int n4 = G >> 2;  // G % 4 == 0 (G = 2500)

    Acc acc;
    #pragma unroll
    for (int k = 0; k < 4; k++) { acc.d[k] = CUDART_INF_F; acc.g[k] = 0; }

    int i = tid;
    // x2 unroll: 4 independent 128-bit streaming loads in flight per thread.
    for (; i + NT < n4; i += 2 * NT) {
        float4 a0 = __ldcs(v0 + i);
        float4 a1 = __ldcs(v0 + i + NT);
        float4 c0 = __ldcs(v1 + i);
        float4 c1 = __ldcs(v1 + i + NT);
        proc4(a0, c0, i << 2,        y0, y1, acc);
        proc4(a1, c1, (i + NT) << 2, y0, y1, acc);
    }
    if (i < n4) {
        float4 a = __ldcs(v0 + i);
        float4 c = __ldcs(v1 + i);
        proc4(a, c, i << 2, y0, y1, acc);
    }

    // Pack and reduce: single u64 min preserves (d2, idx) lexicographic order.
    unsigned long long best = pack(acc.d[0], acc.g[0]);
    #pragma unroll
    for (int k = 1; k < 4; k++) {
        unsigned long long o = pack(acc.d[k], acc.g[k]);
        if (o < best) best = o;
    }

    #pragma unroll
    for (int off = 16; off > 0; off >>= 1) {
        unsigned long long o = __shfl_down_sync(0xffffffffu, best, off);
        if (o < best) best = o;
    }

    __shared__ unsigned long long sb[NT / 32];
    const int w = tid >> 5;
    if ((tid & 31) == 0) sb[w] = best;
    __syncthreads();

    if (w == 0) {
        const int nw = NT / 32;
        best = (tid < nw) ? sb[tid] : 0xffffffffffffffffULL;
        #pragma unroll
        for (int off = 16; off > 0; off >>= 1) {
            unsigned long long o = __shfl_down_sync(0xffffffffu, best, off);
            if (o < best) best = o;
        }
        if (tid == 0) {
            const int bidx = (int)(unsigned)best;
            out[2 * b + 0] = Ug[bidx];
            out[2 * b + 1] = Ug[(size_t)G + bidx];
        }
    }
}

extern "C" void kernel_launch(void* const* d_in, const int* in_sizes, int n_in,
                              void* d_out, int out_size) {
    const float* y  = (const float*)d_in[0];   // [B, 2]
    const float* Ys = (const float*)d_in[1];   // [B, 2, G]
    const float* Ug = (const float*)d_in[2];   // [2, G]
    float* out = (float*)d_out;                // [B, 2]

    const int B = in_sizes[0] / 2;
    const int G = in_sizes[2] / 2;

    lqr_argmin_kernel<<<B, NT>>>(y, Ys, Ug, out, G);
}

// round 6
// speedup vs baseline: 1.0452x; 1.0056x over previous
#include <cuda_runtime.h>
#include <math_constants.h>

// Batched nearest-neighbor argmin + gather (HBM-streaming, ~83% DRAM).
//   y: [B,2] f32, Y_surf: [B,2,G] f32, U_grid: [2,G] f32, out: [B,2] f32
//   out[b,:] = U_grid[:, argmin_g ||Y_surf[b,:,g] - y[b,:]||^2]
//
// Best-of-measured recombination:
//  - Block-per-sample, 128 thr (R1/R3 structure: HW overlaps CTA tails).
//  - Plain LDG float4 x2 unroll (R3: 6579 GB/s; __ldcs measured WORSE twice).
//  - 4 independent argmin accumulators (depth-1 update chains, R3).
//  - Packed u64 (d2bits<<32 | idx) min reduction (R5: shorter tail, 34 regs);
//    d2 >= 0 so IEEE bits are order-monotone -> exact first-index tie-break.

#define NT 128

struct Acc { float d[4]; int g[4]; };

__device__ __forceinline__ void proc4(const float4& a, const float4& c, int g,
                                      float y0, float y1, Acc& acc) {
    float dx, dz, d;
    dx = a.x - y0; dz = c.x - y1; d = dx * dx + dz * dz;
    if (d < acc.d[0]) { acc.d[0] = d; acc.g[0] = g + 0; }
    dx = a.y - y0; dz = c.y - y1; d = dx * dx + dz * dz;
    if (d < acc.d[1]) { acc.d[1] = d; acc.g[1] = g + 1; }
    dx = a.z - y0; dz = c.z - y1; d = dx * dx + dz * dz;
    if (d < acc.d[2]) { acc.d[2] = d; acc.g[2] = g + 2; }
    dx = a.w - y0; dz = c.w - y1; d = dx * dx + dz * dz;
    if (d < acc.d[3]) { acc.d[3] = d; acc.g[3] = g + 3; }
}

__device__ __forceinline__ unsigned long long pack(float d, int g) {
    return ((unsigned long long)__float_as_uint(d) << 32) | (unsigned)g;
}

__global__ __launch_bounds__(NT)
void lqr_argmin_kernel(const float* __restrict__ y,
                       const float* __restrict__ Ys,
                       const float* __restrict__ Ug,
                       float* __restrict__ out,
                       int G) {
    const int b   = blockIdx.x;
    const int tid = threadIdx.x;

    const float y0 = y[2 * b + 0];
    const float y1 = y[2 * b + 1];

    const float4* __restrict__ v0 =
        reinterpret_cast<const float4*>(Ys + (size_t)b * 2 * G);
    const float4* __restrict__ v1 = v0 + (G >> 2);
    const int n4 = G >> 2;  // G % 4 == 0 (G = 2500)

    Acc acc;
    #pragma unroll
    for (int k = 0; k < 4; k++) { acc.d[k] = CUDART_INF_F; acc.g[k] = 0; }

    int i = tid;
    // x2 unroll: 4 independent 128-bit loads in flight per thread.
    for (; i + NT < n4; i += 2 * NT) {
        float4 a0 = v0[i];
        float4 a1 = v0[i + NT];
        float4 c0 = v1[i];
        float4 c1 = v1[i + NT];
        proc4(a0, c0, i << 2,        y0, y1, acc);
        proc4(a1, c1, (i + NT) << 2, y0, y1, acc);
    }
    if (i < n4) {
        float4 a = v0[i];
        float4 c = v1[i];
        proc4(a, c, i << 2, y0, y1, acc);
    }

    // Packed u64 min == (min d2, tie -> min idx) lexicographic.
    unsigned long long best = pack(acc.d[0], acc.g[0]);
    #pragma unroll
    for (int k = 1; k < 4; k++) {
        unsigned long long o = pack(acc.d[k], acc.g[k]);
        if (o < best) best = o;
    }

    #pragma unroll
    for (int off = 16; off > 0; off >>= 1) {
        unsigned long long o = __shfl_down_sync(0xffffffffu, best, off);
        if (o < best) best = o;
    }

    __shared__ unsigned long long sb[NT / 32];
    const int w = tid >> 5;
    if ((tid & 31) == 0) sb[w] = best;
    __syncthreads();

    if (w == 0) {
        const int nw = NT / 32;
        best = (tid < nw) ? sb[tid] : 0xffffffffffffffffULL;
        #pragma unroll
        for (int off = 16; off > 0; off >>= 1) {
            unsigned long long o = __shfl_down_sync(0xffffffffu, best, off);
            if (o < best) best = o;
        }
        if (tid == 0) {
            const int bidx = (int)(unsigned)best;
            out[2 * b + 0] = Ug[bidx];
            out[2 * b + 1] = Ug[(size_t)G + bidx];
        }
    }
}

extern "C" void kernel_launch(void* const* d_in, const int* in_sizes, int n_in,
                              void* d_out, int out_size) {
    const float* y  = (const float*)d_in[0];   // [B, 2]
    const float* Ys = (const float*)d_in[1];   // [B, 2, G]
    const float* Ug = (const float*)d_in[2];   // [2, G]
    float* out = (float*)d_out;                // [B, 2]

    const int B = in_sizes[0] / 2;
    const int G = in_sizes[2] / 2;

    lqr_argmin_kernel<<<B, NT>>>(y, Ys, Ug, out, G);
}